// round 1
// baseline (speedup 1.0000x reference)
#include <cuda_runtime.h>
#include <cstdint>
#include <cub/cub.cuh>

#define DIM   384
#define DIM4  (DIM / 4)
#define MAXM  16
#define MAXN  50000
#define PAV_TPB 256
#define LMAX ((MAXN + PAV_TPB - 1) / PAV_TPB)   // 196

// ---- static device scratch (no allocations allowed) ----
__device__ float         g_qn[MAXM * DIM];
__device__ uint64_t      g_keys_in [MAXM * MAXN];
__device__ uint64_t      g_keys_out[MAXM * MAXN];
__device__ int           g_vals_in [MAXM * MAXN];
__device__ int           g_vals_out[MAXM * MAXN];
__device__ double        g_csum[MAXM * MAXN];
__device__ int           g_ccnt[MAXM * MAXN];
__device__ double        g_ssum[MAXM * MAXN];
__device__ int           g_scnt[MAXM * MAXN];
__device__ int           g_sbnd[MAXM * MAXN];
__device__ unsigned char g_temp[48u * 1024u * 1024u];

// ---------------- query normalization ----------------
__global__ void qnorm_kernel(const float* __restrict__ q, int M) {
    int row = blockIdx.x;
    float ss = 0.f;
    for (int i = threadIdx.x; i < DIM; i += blockDim.x) {
        float v = q[row * DIM + i];
        ss += v * v;
    }
    __shared__ float red[128];
    red[threadIdx.x] = ss;
    __syncthreads();
    for (int s = 64; s > 0; s >>= 1) {
        if (threadIdx.x < s) red[threadIdx.x] += red[threadIdx.x + s];
        __syncthreads();
    }
    float inv = 1.f / fmaxf(sqrtf(red[0]), 1e-12f);
    for (int i = threadIdx.x; i < DIM; i += blockDim.x)
        g_qn[row * DIM + i] = q[row * DIM + i] * inv;
}

// ---------------- cosine similarity GEMM ----------------
// 8 warps/block, 4 docs/warp. Queries cached in SMEM as float4.
#define DPW 4
__global__ void sim_kernel(const float4* __restrict__ corpus4,
                           float* __restrict__ sims, int M, int N) {
    __shared__ float4 qs[MAXM * DIM4];   // 24 KB
    for (int i = threadIdx.x; i < MAXM * DIM4; i += blockDim.x)
        qs[i] = ((const float4*)g_qn)[i];
    __syncthreads();

    int warp = threadIdx.x >> 5, lane = threadIdx.x & 31;
    int dbase = (blockIdx.x * 8 + warp) * DPW;

    float acc[DPW][16];
    float ss[DPW];
#pragma unroll
    for (int d = 0; d < DPW; d++) {
        ss[d] = 0.f;
#pragma unroll
        for (int q = 0; q < 16; q++) acc[d][q] = 0.f;
    }

    bool full = (dbase + DPW <= N);
    for (int k = lane; k < DIM4; k += 32) {
        float4 v[DPW];
#pragma unroll
        for (int d = 0; d < DPW; d++) {
            int doc = dbase + d;
            if (full || doc < N)
                v[d] = corpus4[(size_t)doc * DIM4 + k];
            else
                v[d] = make_float4(0.f, 0.f, 0.f, 0.f);
            ss[d] += v[d].x * v[d].x + v[d].y * v[d].y +
                     v[d].z * v[d].z + v[d].w * v[d].w;
        }
#pragma unroll
        for (int q = 0; q < 16; q++) {
            float4 qq = qs[q * DIM4 + k];
#pragma unroll
            for (int d = 0; d < DPW; d++) {
                acc[d][q] += qq.x * v[d].x + qq.y * v[d].y +
                             qq.z * v[d].z + qq.w * v[d].w;
            }
        }
    }

    // warp butterfly reduction
#pragma unroll
    for (int off = 16; off; off >>= 1) {
#pragma unroll
        for (int d = 0; d < DPW; d++) {
            ss[d] += __shfl_xor_sync(0xffffffffu, ss[d], off);
#pragma unroll
            for (int q = 0; q < 16; q++)
                acc[d][q] += __shfl_xor_sync(0xffffffffu, acc[d][q], off);
        }
    }

    __shared__ float st[8 * DPW * 16];   // [doc_in_block][q]
    if (lane == 0) {
#pragma unroll
        for (int d = 0; d < DPW; d++) {
            float inv = 1.f / fmaxf(sqrtf(ss[d]), 1e-12f);
#pragma unroll
            for (int q = 0; q < 16; q++)
                st[(warp * DPW + d) * 16 + q] = acc[d][q] * inv;
        }
    }
    __syncthreads();

    int blockbase = blockIdx.x * (8 * DPW);
    for (int i = threadIdx.x; i < 8 * DPW * M; i += blockDim.x) {
        int q = i / (8 * DPW);
        int w = i - q * (8 * DPW);
        int doc = blockbase + w;
        if (doc < N) sims[(size_t)q * N + doc] = st[w * 16 + q];
    }
}

// ---------------- key/value fill for fused radix sort ----------------
__global__ void keyfill_kernel(const float* __restrict__ sims, int M, int N) {
    int i = blockIdx.x * blockDim.x + threadIdx.x;
    int total = M * N;
    if (i < total) {
        int row = i / N;
        int col = i - row * N;
        unsigned u = __float_as_uint(sims[i]);
        u = (u & 0x80000000u) ? ~u : (u | 0x80000000u);   // ascending-sortable
        g_keys_in[i] = ((uint64_t)row << 32) | (uint64_t)u;
        g_vals_in[i] = col;
    }
}

__device__ __forceinline__ float decode_key(uint64_t k) {
    unsigned u = (unsigned)(k & 0xffffffffu);
    return (u & 0x80000000u) ? __uint_as_float(u ^ 0x80000000u)
                             : __uint_as_float(~u);
}

// ---------------- parallel PAV (nonincreasing isotonic regression) ----------
// One block per row. Phase 1: per-thread chunk PAV. Phase 2: thread-0 merges
// chunk block lists (PAV over pooled blocks, register-cached stack top).
// Phase 3: all threads binary-search their block, compute primal, scatter.
__global__ void pav_kernel(float* __restrict__ ranks, int M, int N) {
    int row = blockIdx.x;
    const uint64_t* keys = g_keys_out + (size_t)row * N;
    const int*      idxs = g_vals_out + (size_t)row * N;
    double* csum = g_csum + (size_t)row * N;
    int*    ccnt = g_ccnt + (size_t)row * N;
    double* ssum = g_ssum + (size_t)row * N;
    int*    scnt = g_scnt + (size_t)row * N;
    int*    sbnd = g_sbnd + (size_t)row * N;

    int t = threadIdx.x;
    int L = (N + PAV_TPB - 1) / PAV_TPB;       // <= LMAX
    int j0 = min(t * L, N);
    int j1 = min(j0 + L, N);

    __shared__ int    snb[PAV_TPB];
    __shared__ double s1sum[PAV_TPB];
    __shared__ int    s1cnt[PAV_TPB];
    __shared__ int    sP;

    // --- phase 1: chunk PAV with register-cached top ---
    double lsum[LMAX];
    int    lcnt[LMAX];
    double topS = 0.0;
    int    topC = 0;
    int p = 0;   // number of blocks; top block (index p-1) lives in regs
    for (int j = j0; j < j1; j++) {
        float f = decode_key(keys[j]);
        double cs = -10.0 * (double)f - (double)(N - j);   // y_j = s_j - (n - j)
        int cc = 1;
        // merge while prev_mean < cur_mean
        while (p > 0 && topS * (double)cc < cs * (double)topC) {
            cs += topS; cc += topC; p--;
            if (p > 0) { topS = lsum[p - 1]; topC = lcnt[p - 1]; }
        }
        if (p > 0) { lsum[p - 1] = topS; lcnt[p - 1] = topC; }
        topS = cs; topC = cc; p++;
    }
    if (p > 0) { lsum[p - 1] = topS; lcnt[p - 1] = topC; }
    for (int b = 0; b < p; b++) { csum[j0 + b] = lsum[b]; ccnt[j0 + b] = lcnt[b]; }
    snb[t] = p;
    if (p >= 1) { s1sum[t] = lsum[0]; s1cnt[t] = lcnt[0]; }
    __syncthreads();

    // --- phase 2: sequential merge of chunk block lists ---
    if (t == 0) {
        int P = 0;
        double TS = 0.0; int TC = 0;   // register-cached stack top
        for (int tt = 0; tt < PAV_TPB; tt++) {
            int nb = snb[tt];
            int base = tt * L;
            for (int b = 0; b < nb; b++) {
                double cs; int cc;
                if (b == 0) { cs = s1sum[tt]; cc = s1cnt[tt]; }
                else        { cs = csum[base + b]; cc = ccnt[base + b]; }
                while (P > 0 && TS * (double)cc < cs * (double)TC) {
                    cs += TS; cc += TC; P--;
                    if (P > 0) { TS = ssum[P - 1]; TC = scnt[P - 1]; }
                }
                if (P > 0) { ssum[P - 1] = TS; scnt[P - 1] = TC; }
                TS = cs; TC = cc; P++;
            }
        }
        if (P > 0) { ssum[P - 1] = TS; scnt[P - 1] = TC; }
        int acc = 0;
        for (int b = 0; b < P; b++) { acc += scnt[b]; sbnd[b] = acc; }
        sP = P;
    }
    __syncthreads();

    // --- phase 3: per-element dual lookup + scatter primal ---
    int P = sP;
    for (int j = t; j < N; j += PAV_TPB) {
        int lo = 0, hi = P - 1;
        while (lo < hi) {
            int mid = (lo + hi) >> 1;
            if (sbnd[mid] > j) hi = mid; else lo = mid + 1;
        }
        double dual = ssum[lo] / (double)scnt[lo];
        double s = -10.0 * (double)decode_key(keys[j]);
        ranks[(size_t)row * N + idxs[j]] = (float)(s - dual);
    }
}

// ---------------- host launch ----------------
extern "C" void kernel_launch(void* const* d_in, const int* in_sizes, int n_in,
                              void* d_out, int out_size) {
    const float* q      = (const float*)d_in[0];
    const float* corpus = (const float*)d_in[1];
    int M = in_sizes[0] / DIM;   // 16
    int N = in_sizes[1] / DIM;   // 50000
    if (M > MAXM) M = MAXM;
    if (N > MAXN) N = MAXN;

    float* sims  = (float*)d_out;
    float* ranks = sims + (size_t)M * N;

    qnorm_kernel<<<M, 128>>>(q, M);

    int docs_per_block = 8 * DPW;   // 32
    sim_kernel<<<(N + docs_per_block - 1) / docs_per_block, 256>>>(
        (const float4*)corpus, sims, M, N);

    int total = M * N;
    keyfill_kernel<<<(total + 255) / 256, 256>>>(sims, M, N);

    void *p_kin, *p_kout, *p_vin, *p_vout, *p_temp;
    cudaGetSymbolAddress(&p_kin,  g_keys_in);
    cudaGetSymbolAddress(&p_kout, g_keys_out);
    cudaGetSymbolAddress(&p_vin,  g_vals_in);
    cudaGetSymbolAddress(&p_vout, g_vals_out);
    cudaGetSymbolAddress(&p_temp, g_temp);

    int rb = 0;
    while ((1 << rb) < M) rb++;
    int end_bit = 32 + rb;          // 36 for M=16

    size_t temp_bytes = 0;
    cub::DeviceRadixSort::SortPairs(nullptr, temp_bytes,
        (const uint64_t*)p_kin, (uint64_t*)p_kout,
        (const int*)p_vin, (int*)p_vout, total, 0, end_bit, (cudaStream_t)0);
    if (temp_bytes <= sizeof(g_temp)) {
        cub::DeviceRadixSort::SortPairs(p_temp, temp_bytes,
            (const uint64_t*)p_kin, (uint64_t*)p_kout,
            (const int*)p_vin, (int*)p_vout, total, 0, end_bit, (cudaStream_t)0);
    }

    pav_kernel<<<M, PAV_TPB>>>(ranks, M, N);
}